// round 14
// baseline (speedup 1.0000x reference)
#include <cuda_runtime.h>
#include <math.h>

#define Bs   16
#define Cc   256
#define Hh   128
#define Ww   128
#define HW   16384
#define CHUNK 2          // batches per pipeline stage
#define PIX  32          // pixels per block (both phases)
#define SS   258         // smem row stride (words): even -> 8B-aligned LDS.64
#define EPSV 1e-05f
#define TSTRIDE 1064     // words per transpose tile (32*33 + 8 pad)

// FOUR 16MB scratch slices (64 MB total, L2-resident): batch b uses slice b&3.
// Slice reuse (batch b+4) happens two launches after div(b) consumed it —
// ordered by the single-stream launch sequence, no events needed. g_att full
// size [Bs][HW] (batch-disjoint). Zero-initialized at load; div restores zeros
// after consumption (separate pass AFTER reads complete — R3 lesson: never
// store to a line with a pending same-thread load miss), so graph replays are
// deterministic. Streaming data (x, out, offo) uses evict-first hints
// (__ldcs/__stcs) so it cannot evict scratch from L2.
__device__ float g_feat[(size_t)4 * HW * Cc];
__device__ float g_att[(size_t)Bs * HW];

// ---------------- scatter body (R11-proven, NUMERICS FROZEN) ----------------
// Strided-by-8 fp32 summation order (warp w owns channels {8k+w}, serial fmaf
// over k; warp0 reduce in w-order seeded with cb) correlates with the
// reference's own fp32 rounding at round(dest) boundaries -> rel_err
// 8.8778e-4 stable. Do not reorder.
__device__ __forceinline__ void scatter_body(
    float* pool, const float* __restrict__ x, const float* __restrict__ cw,
    const float* __restrict__ cb, float* __restrict__ offo,
    float* feat, int b, int hw0) {
    float* s_x   = pool;               // [PIX*SS] 8256 floats
    float* s_w   = pool + 8256;        // 768
    float* s_red = pool + 9024;        // 768
    __shared__ float s_att[PIX];
    __shared__ int   s_idx[PIX];

    const int tid  = threadIdx.x;
    const int lane = tid & 31;
    const int warp = tid >> 5;

    for (int i = tid; i < 3 * Cc; i += 256) s_w[i] = cw[i];
    __syncthreads();

    const float* xb = x + (size_t)b * Cc * HW + hw0;
    float a0 = 0.f, a1 = 0.f, a2 = 0.f;
#pragma unroll
    for (int k = 0; k < Cc / 8; k++) {
        int c = k * 8 + warp;                         // warp owns channel slice
        float v = __ldcs(xb + (size_t)c * HW + lane); // streaming: read-once x
        s_x[lane * SS + c] = v;
        a0 = fmaf(v, s_w[c],          a0);
        a1 = fmaf(v, s_w[Cc + c],     a1);
        a2 = fmaf(v, s_w[2 * Cc + c], a2);
    }
    s_red[(0 * 8 + warp) * 32 + lane] = a0;
    s_red[(1 * 8 + warp) * 32 + lane] = a1;
    s_red[(2 * 8 + warp) * 32 + lane] = a2;
    __syncthreads();

    if (warp == 0) {                    // lane == pixel within tile
        float r0 = cb[0], r1 = cb[1], r2 = cb[2];
#pragma unroll
        for (int w = 0; w < 8; w++) {
            r0 += s_red[w * 32 + lane];
            r1 += s_red[(8 + w) * 32 + lane];
            r2 += s_red[(16 + w) * 32 + lane];
        }
        float offy = r0 * (float)Hh;
        float offx = r1 * (float)Ww;
        float att  = expf(r2);
        int hw = hw0 + lane;
        int hh = hw >> 7, wc = hw & 127;
        // round-half-even (rintf) then clip, matching jnp.round + clip
        int iy = (int)fminf(fmaxf(rintf((float)hh + offy), 0.f), 127.f);
        int ix = (int)fminf(fmaxf(rintf((float)wc + offx), 0.f), 127.f);
        int idx = (iy << 7) + ix;
        s_att[lane] = att;
        s_idx[lane] = idx;
        size_t ob = (size_t)b * 2 * HW + hw;       // offset: [B][2][H][W]
        __stcs(offo + ob,      offy);              // streaming: write-once
        __stcs(offo + ob + HW, offx);
        atomicAdd(&g_att[(size_t)b * HW + idx], att);
    }
    __syncthreads();

    // Scatter: each warp handles 4 pixels; per pixel, 2 x red.v4 per lane
    // covering a contiguous 1KB destination row feat[idx][:].
#pragma unroll
    for (int p = warp; p < PIX; p += 8) {
        float att = s_att[p];
        float* dst = feat + (size_t)s_idx[p] * Cc;
        const float* src = s_x + p * SS;
#pragma unroll
        for (int r = 0; r < 2; r++) {
            int c0 = r * 128 + 4 * lane;
            float2 u = *reinterpret_cast<const float2*>(src + c0);
            float2 v = *reinterpret_cast<const float2*>(src + c0 + 2);
            asm volatile(
                "red.global.add.v4.f32 [%0], {%1, %2, %3, %4};" ::
                "l"(dst + c0),
                "f"(u.x * att), "f"(u.y * att), "f"(v.x * att), "f"(v.y * att)
                : "memory");
        }
    }
}

// ------------------- div body (R11-proven STG.128 version) ------------------
__device__ __forceinline__ void div_body(
    float* pool, float* __restrict__ out, float* feat, int b, int hw0) {
    float* t = pool;                    // [8*TSTRIDE] 8512 floats
    __shared__ __align__(16) float inv[32];
    const int tid = threadIdx.x;

    if (tid < 32)
        inv[tid] = 1.0f / (g_att[(size_t)b * HW + hw0 + tid] + EPSV);

    const float4* src = reinterpret_cast<const float4*>(feat + (size_t)hw0 * Cc);
#pragma unroll
    for (int k = 0; k < 8; k++) {
        int i  = tid + k * 256;         // [0, 2048)
        int hw = i >> 6;                // 0..31 (pixel)
        int cq = i & 63;                // float4 index within 256 channels
        float4 v = src[i];
        int g  = cq >> 3;               // channel group (tile)
        int cc = (cq & 7) * 4;          // channel within tile
        float* d = &t[g * TSTRIDE + hw * 33 + cc];
        d[0] = v.x; d[1] = v.y; d[2] = v.z; d[3] = v.w;
    }
    __syncthreads();

    const int lane = tid & 31;
    const int g    = tid >> 5;          // warp -> channel group
    const int q    = lane >> 2;         // hw quad (4q..4q+3)
    const int jl   = lane & 3;          // channel sub-lane
    const float4 iv = *reinterpret_cast<const float4*>(&inv[4 * q]);
    const float* tg = &t[g * TSTRIDE];
#pragma unroll
    for (int it = 0; it < 8; it++) {
        const int cc = it * 4 + jl;     // channel within group
        float4 o;
        o.x = tg[(4 * q + 0) * 33 + cc] * iv.x;
        o.y = tg[(4 * q + 1) * 33 + cc] * iv.y;
        o.z = tg[(4 * q + 2) * 33 + cc] * iv.z;
        o.w = tg[(4 * q + 3) * 33 + cc] * iv.w;
        __stcs(reinterpret_cast<float4*>(
            out + ((size_t)b * Cc + g * 32 + cc) * HW + hw0 + 4 * q), o);
    }

    // Re-zero this block's scratch region (all loads above completed).
    float4* fz = reinterpret_cast<float4*>(feat + (size_t)hw0 * Cc);
    float4 z = make_float4(0.f, 0.f, 0.f, 0.f);
#pragma unroll
    for (int k = 0; k < 8; k++)
        fz[tid + k * 256] = z;
    if (tid < 32)
        g_att[(size_t)b * HW + hw0 + tid] = 0.f;
}

// --------------------------- fused pipeline kernel --------------------------
// mode 0: 2048 blocks, even = scatter(chunk bs0/2), odd = div(chunk bd0/2).
// mode 1: 1024 blocks, scatter only.   mode 2: 1024 blocks, div only.
__global__ __launch_bounds__(256) void k_both(
    const float* __restrict__ x, const float* __restrict__ cw,
    const float* __restrict__ cb, float* __restrict__ offo,
    float* __restrict__ out, int bs0, int bd0, int mode) {
    __shared__ float pool[9792];        // union: scatter 9792 / div 8512 floats

    int type, wb;
    if (mode == 0) { type = blockIdx.x & 1; wb = blockIdx.x >> 1; }
    else           { type = mode - 1;       wb = blockIdx.x;      }

    const int b   = (type ? bd0 : bs0) + (wb >> 9);   // 512 blocks per batch
    const int hw0 = (wb & 511) * PIX;
    float* feat = g_feat + (size_t)(b & 3) * HW * Cc;

    if (type == 0)
        scatter_body(pool, x, cw, cb, offo, feat, b, hw0);
    else
        div_body(pool, out, feat, b, hw0);
}

// ---------------------------------------------------------------- launch
// Software pipeline over 8 chunks on ONE stream: launch c runs scatter(c)
// alongside div(c-1). 9 launches total, no events. Launch boundaries provide
// all ordering (scatter(c) completes before div(c) in launch c+1; slice b&3
// reused by scatter(b+4) two launches after div(b)).
extern "C" void kernel_launch(void* const* d_in, const int* in_sizes, int n_in,
                              void* d_out, int out_size) {
    const float* x  = (const float*)d_in[0];   // [16,256,128,128]
    const float* cw = (const float*)d_in[1];   // [3,256]
    const float* cb = (const float*)d_in[2];   // [3]
    float* out  = (float*)d_out;                        // [B,C,HW]
    float* offo = out + (size_t)Bs * Cc * HW;           // [B,2,H,W]

    const int NCH = Bs / CHUNK;        // 8 chunks
    k_both<<<1024, 256>>>(x, cw, cb, offo, out, 0, 0, 1);            // scatter(0)
    for (int c = 1; c < NCH; c++)
        k_both<<<2048, 256>>>(x, cw, cb, offo, out,
                              c * CHUNK, (c - 1) * CHUNK, 0);        // sc(c)+div(c-1)
    k_both<<<1024, 256>>>(x, cw, cb, offo, out, 0, (NCH - 1) * CHUNK, 2); // div(7)
}

// round 15
// speedup vs baseline: 1.0281x; 1.0281x over previous
#include <cuda_runtime.h>
#include <math.h>

#define Bs   16
#define Cc   256
#define Hh   128
#define Ww   128
#define HW   16384
#define NSLC 4           // ping-pong scratch slices / streams
#define PIX  32          // pixels per scatter block
#define SS   264         // smem row stride (words): 1056B = 16B-aligned rows -> LDS.128
#define EPSV 1e-05f
#define TSTRIDE 1064     // words per transpose tile (32*33 + 8 pad)

// FOUR ping-pong scratch slices [NSLC][HW][C] (16 MB each, 64 MB total,
// L2-resident): batch b uses slice b%4 on stream b%4, so up to 4 independent
// (scatter,div) pairs co-run (2 suffice to saturate; 4 is harmless). g_att
// full size [Bs][HW] (batch-disjoint). Zero-initialized at load; k_div
// restores zeros after consumption (separate pass AFTER reads complete — R3
// lesson: never store to a line with a pending same-thread load miss), so
// graph replays are deterministic. Streaming data (x, out, offo) uses
// evict-first hints (__ldcs/__stcs) so it cannot evict scratch from L2.
__device__ float g_feat[(size_t)NSLC * HW * Cc];
__device__ float g_att[(size_t)Bs * HW];

// -------------------------------------------- fused conv + scatter
// NUMERICS FROZEN (R8/R9 lesson): the strided-by-8 fp32 summation order
// (warp w owns channels {8k+w}, serial fmaf over k; warp0 reduce in w-order
// seeded with cb) correlates with the reference's own fp32 rounding at the
// round(dest) boundaries -> rel_err 8.8778e-4 stable. Do not reorder.
// Warp0-serial reduce is faster than redundant-all-warps (R13 measurement).
__global__ __launch_bounds__(256) void k_scatter(
    const float* __restrict__ x, const float* __restrict__ cw,
    const float* __restrict__ cb, float* __restrict__ offo, int b, int slc) {
    __shared__ float s_x[PIX * SS];     // 33.8 KB tile, [pixel][channel]
    __shared__ float s_w[3 * Cc];
    __shared__ float s_red[3 * 8 * 32];
    __shared__ float s_att[PIX];
    __shared__ int   s_idx[PIX];

    const int tid  = threadIdx.x;
    const int lane = tid & 31;
    const int warp = tid >> 5;
    const int hw0  = blockIdx.x * PIX;
    float* feat = g_feat + (size_t)slc * HW * Cc;

    for (int i = tid; i < 3 * Cc; i += 256) s_w[i] = cw[i];
    __syncthreads();

    const float* xb = x + (size_t)b * Cc * HW + hw0;
    float a0 = 0.f, a1 = 0.f, a2 = 0.f;
#pragma unroll
    for (int k = 0; k < Cc / 8; k++) {
        int c = k * 8 + warp;                         // warp owns channel slice
        float v = __ldcs(xb + (size_t)c * HW + lane); // streaming: read-once x
        s_x[lane * SS + c] = v;
        a0 = fmaf(v, s_w[c],          a0);
        a1 = fmaf(v, s_w[Cc + c],     a1);
        a2 = fmaf(v, s_w[2 * Cc + c], a2);
    }
    s_red[(0 * 8 + warp) * 32 + lane] = a0;
    s_red[(1 * 8 + warp) * 32 + lane] = a1;
    s_red[(2 * 8 + warp) * 32 + lane] = a2;
    __syncthreads();

    if (warp == 0) {                    // lane == pixel within tile
        float r0 = cb[0], r1 = cb[1], r2 = cb[2];
#pragma unroll
        for (int w = 0; w < 8; w++) {
            r0 += s_red[w * 32 + lane];
            r1 += s_red[(8 + w) * 32 + lane];
            r2 += s_red[(16 + w) * 32 + lane];
        }
        float offy = r0 * (float)Hh;
        float offx = r1 * (float)Ww;
        float att  = expf(r2);
        int hw = hw0 + lane;
        int hh = hw >> 7, wc = hw & 127;
        // round-half-even (rintf) then clip, matching jnp.round + clip
        int iy = (int)fminf(fmaxf(rintf((float)hh + offy), 0.f), 127.f);
        int ix = (int)fminf(fmaxf(rintf((float)wc + offx), 0.f), 127.f);
        int idx = (iy << 7) + ix;
        s_att[lane] = att;
        s_idx[lane] = idx;
        size_t ob = (size_t)b * 2 * HW + hw;       // offset: [B][2][H][W]
        __stcs(offo + ob,      offy);              // streaming: write-once
        __stcs(offo + ob + HW, offx);
        atomicAdd(&g_att[(size_t)b * HW + idx], att);
    }
    __syncthreads();

    // Scatter: each warp handles 4 pixels; per pixel, 2 x (LDS.128 + red.v4)
    // per lane covering a contiguous 1KB destination row feat[idx][:].
    // Rows are 16B-aligned (SS=264) -> single vector load per quad.
#pragma unroll
    for (int p = warp; p < PIX; p += 8) {
        float att = s_att[p];
        float* dst = feat + (size_t)s_idx[p] * Cc;
        const float4* src = reinterpret_cast<const float4*>(s_x + p * SS);
#pragma unroll
        for (int r = 0; r < 2; r++) {
            float4 u = src[r * 32 + lane];          // channels r*128+4*lane..+3
            asm volatile(
                "red.global.add.v4.f32 [%0], {%1, %2, %3, %4};" ::
                "l"(dst + r * 128 + 4 * lane),
                "f"(u.x * att), "f"(u.y * att), "f"(u.z * att), "f"(u.w * att)
                : "memory");
        }
    }
}

// ----------------- normalize + transpose to [B][C][HW] + re-zero scratch
// Load phase: 8 independent coalesced LDG.128 per thread (MLP=8) into 8
// padded 32x33 smem tiles; ONE barrier. Store phase: warp g owns channel
// group g; lane (q=l>>2, jl=l&3) gathers 4 hw values per channel
// (conflict-free) and writes streaming STG.128. inv applied per hw component.
__global__ __launch_bounds__(256) void k_div(float* __restrict__ out, int b,
                                             int slc) {
    __shared__ float t[8 * TSTRIDE];    // ~34 KB
    __shared__ __align__(16) float inv[32];
    const int tid = threadIdx.x;
    const int hw0 = blockIdx.x * 32;
    float* feat = g_feat + (size_t)slc * HW * Cc;

    if (tid < 32)
        inv[tid] = 1.0f / (g_att[(size_t)b * HW + hw0 + tid] + EPSV);

    const float4* src = reinterpret_cast<const float4*>(feat + (size_t)hw0 * Cc);
#pragma unroll
    for (int k = 0; k < 8; k++) {
        int i  = tid + k * 256;         // [0, 2048)
        int hw = i >> 6;                // 0..31 (pixel)
        int cq = i & 63;                // float4 index within 256 channels
        float4 v = src[i];
        int g  = cq >> 3;               // channel group (tile)
        int cc = (cq & 7) * 4;          // channel within tile
        float* d = &t[g * TSTRIDE + hw * 33 + cc];
        d[0] = v.x; d[1] = v.y; d[2] = v.z; d[3] = v.w;
    }
    __syncthreads();

    const int lane = tid & 31;
    const int g    = tid >> 5;          // warp -> channel group
    const int q    = lane >> 2;         // hw quad (4q..4q+3)
    const int jl   = lane & 3;          // channel sub-lane
    const float4 iv = *reinterpret_cast<const float4*>(&inv[4 * q]);
    const float* tg = &t[g * TSTRIDE];
#pragma unroll
    for (int it = 0; it < 8; it++) {
        const int cc = it * 4 + jl;     // channel within group
        float4 o;
        o.x = tg[(4 * q + 0) * 33 + cc] * iv.x;
        o.y = tg[(4 * q + 1) * 33 + cc] * iv.y;
        o.z = tg[(4 * q + 2) * 33 + cc] * iv.z;
        o.w = tg[(4 * q + 3) * 33 + cc] * iv.w;
        __stcs(reinterpret_cast<float4*>(
            out + ((size_t)b * Cc + g * 32 + cc) * HW + hw0 + 4 * q), o);
    }

    // Re-zero this block's scratch region (all loads above completed).
    float4* fz = reinterpret_cast<float4*>(feat + (size_t)hw0 * Cc);
    float4 z = make_float4(0.f, 0.f, 0.f, 0.f);
#pragma unroll
    for (int k = 0; k < 8; k++)
        fz[tid + k * 256] = z;
    if (tid < 32)
        g_att[(size_t)b * HW + hw0 + tid] = 0.f;
}

// ---------------------------------------------------------------- launch
// 16 independent (scatter,div) pairs, one batch each, round-robin over 4
// streams (origin + 3) with capture-safe event fork/join. Scratch slice
// reuse within a stream is ordered by stream order.
extern "C" void kernel_launch(void* const* d_in, const int* in_sizes, int n_in,
                              void* d_out, int out_size) {
    const float* x  = (const float*)d_in[0];   // [16,256,128,128]
    const float* cw = (const float*)d_in[1];   // [3,256]
    const float* cb = (const float*)d_in[2];   // [3]
    float* out  = (float*)d_out;                        // [B,C,HW]
    float* offo = out + (size_t)Bs * Cc * HW;           // [B,2,H,W]

    static cudaStream_t st[NSLC] = {nullptr, nullptr, nullptr, nullptr};
    static cudaEvent_t  efork = nullptr;
    static cudaEvent_t  ejoin[NSLC] = {nullptr, nullptr, nullptr, nullptr};
    if (efork == nullptr) {            // host-side resource init only
        st[0] = (cudaStream_t)0;       // capture-origin stream
        cudaEventCreateWithFlags(&efork, cudaEventDisableTiming);
        for (int i = 1; i < NSLC; i++) {
            cudaStreamCreateWithFlags(&st[i], cudaStreamNonBlocking);
            cudaEventCreateWithFlags(&ejoin[i], cudaEventDisableTiming);
        }
    }

    cudaEventRecord(efork, st[0]);
    for (int i = 1; i < NSLC; i++)
        cudaStreamWaitEvent(st[i], efork, 0);

    for (int b = 0; b < Bs; b++) {
        const int s = b & (NSLC - 1);
        k_scatter<<<HW / PIX, 256, 0, st[s]>>>(x, cw, cb, offo, b, s);
        k_div<<<HW / 32, 256, 0, st[s]>>>(out, b, s);
    }

    for (int i = 1; i < NSLC; i++) {
        cudaEventRecord(ejoin[i], st[i]);
        cudaStreamWaitEvent(st[0], ejoin[i], 0);
    }
}

// round 16
// speedup vs baseline: 1.1675x; 1.1356x over previous
#include <cuda_runtime.h>
#include <math.h>

#define Bs   16
#define Cc   256
#define Hh   128
#define Ww   128
#define HW   16384
#define NSLC 4           // ping-pong scratch slices / streams
#define PIX  32          // pixels per scatter block
#define SS   258         // smem row stride: lane*258 mod 32 = 2-way STS conflict (best found)
#define EPSV 1e-05f
#define TSTRIDE 1064     // words per transpose tile (32*33 + 8 pad)

// FOUR ping-pong scratch slices [NSLC][HW][C] (16 MB each, 64 MB total,
// L2-resident): batch b uses slice b%4 on stream b%4. g_att full size
// [Bs][HW] (batch-disjoint). Zero-initialized at load; k_div restores zeros
// after consumption (separate pass AFTER reads complete — R3 lesson: never
// store to a line with a pending same-thread load miss), so graph replays
// are deterministic. Streaming data (x, out, offo) uses evict-first hints
// (__ldcs/__stcs) so it cannot evict scratch from L2.
__device__ float g_feat[(size_t)NSLC * HW * Cc];
__device__ float g_att[(size_t)Bs * HW];

// -------------------------------------------- fused conv + scatter
// NUMERICS FROZEN (R8/R9 lesson): the strided-by-8 fp32 summation order
// (warp w owns channels {8k+w}, serial fmaf over k; warp0 reduce in w-order
// seeded with cb) correlates with the reference's own fp32 rounding at the
// round(dest) boundaries -> rel_err 8.8778e-4 stable. Do not reorder.
// R15 change: warp0 publishes s_att/s_idx BEFORE the barrier and defers its
// offo stores + g_att atomic until after it — the barrier no longer waits on
// warp0's global-store/atomic latency.
__global__ __launch_bounds__(256) void k_scatter(
    const float* __restrict__ x, const float* __restrict__ cw,
    const float* __restrict__ cb, float* __restrict__ offo, int b, int slc) {
    __shared__ float s_x[PIX * SS];     // 33 KB tile, [pixel][channel]
    __shared__ float s_w[3 * Cc];
    __shared__ float s_red[3 * 8 * 32];
    __shared__ float s_att[PIX];
    __shared__ int   s_idx[PIX];

    const int tid  = threadIdx.x;
    const int lane = tid & 31;
    const int warp = tid >> 5;
    const int hw0  = blockIdx.x * PIX;
    float* feat = g_feat + (size_t)slc * HW * Cc;

    for (int i = tid; i < 3 * Cc; i += 256) s_w[i] = cw[i];
    __syncthreads();

    const float* xb = x + (size_t)b * Cc * HW + hw0;
    float a0 = 0.f, a1 = 0.f, a2 = 0.f;
#pragma unroll
    for (int k = 0; k < Cc / 8; k++) {
        int c = k * 8 + warp;                         // warp owns channel slice
        float v = __ldcs(xb + (size_t)c * HW + lane); // streaming: read-once x
        s_x[lane * SS + c] = v;
        a0 = fmaf(v, s_w[c],          a0);
        a1 = fmaf(v, s_w[Cc + c],     a1);
        a2 = fmaf(v, s_w[2 * Cc + c], a2);
    }
    s_red[(0 * 8 + warp) * 32 + lane] = a0;
    s_red[(1 * 8 + warp) * 32 + lane] = a1;
    s_red[(2 * 8 + warp) * 32 + lane] = a2;
    __syncthreads();

    float offy = 0.f, offx = 0.f, att = 0.f;
    int idx = 0;
    if (warp == 0) {                    // lane == pixel within tile
        float r0 = cb[0], r1 = cb[1], r2 = cb[2];
#pragma unroll
        for (int w = 0; w < 8; w++) {
            r0 += s_red[w * 32 + lane];
            r1 += s_red[(8 + w) * 32 + lane];
            r2 += s_red[(16 + w) * 32 + lane];
        }
        offy = r0 * (float)Hh;
        offx = r1 * (float)Ww;
        att  = expf(r2);
        int hw = hw0 + lane;
        int hh = hw >> 7, wc = hw & 127;
        // round-half-even (rintf) then clip, matching jnp.round + clip
        int iy = (int)fminf(fmaxf(rintf((float)hh + offy), 0.f), 127.f);
        int ix = (int)fminf(fmaxf(rintf((float)wc + offx), 0.f), 127.f);
        idx = (iy << 7) + ix;
        s_att[lane] = att;              // publish for the other warps…
        s_idx[lane] = idx;
    }
    __syncthreads();

    if (warp == 0) {                    // …then do global writes off-path
        size_t ob = (size_t)b * 2 * HW + hw0 + lane;  // offset: [B][2][H][W]
        __stcs(offo + ob,      offy);                 // streaming: write-once
        __stcs(offo + ob + HW, offx);
        atomicAdd(&g_att[(size_t)b * HW + idx], att);
    }

    // Scatter: each warp handles 4 pixels; per pixel, 2 x red.v4 per lane
    // covering a contiguous 1KB destination row feat[idx][:].
#pragma unroll
    for (int p = warp; p < PIX; p += 8) {
        float attp = s_att[p];
        float* dst = feat + (size_t)s_idx[p] * Cc;
        const float* src = s_x + p * SS;
#pragma unroll
        for (int r = 0; r < 2; r++) {
            int c0 = r * 128 + 4 * lane;
            float2 u = *reinterpret_cast<const float2*>(src + c0);
            float2 v = *reinterpret_cast<const float2*>(src + c0 + 2);
            asm volatile(
                "red.global.add.v4.f32 [%0], {%1, %2, %3, %4};" ::
                "l"(dst + c0),
                "f"(u.x * attp), "f"(u.y * attp),
                "f"(v.x * attp), "f"(v.y * attp)
                : "memory");
        }
    }
}

// ----------------- normalize + transpose to [B][C][HW] + re-zero scratch
// Load phase: 8 independent coalesced LDG.128 per thread (MLP=8) into 8
// padded 32x33 smem tiles; ONE barrier. Store phase: warp g owns channel
// group g; lane (q=l>>2, jl=l&3) gathers 4 hw values per channel
// (conflict-free) and writes streaming STG.128. inv applied per hw component.
__global__ __launch_bounds__(256) void k_div(float* __restrict__ out, int b,
                                             int slc) {
    __shared__ float t[8 * TSTRIDE];    // ~34 KB
    __shared__ __align__(16) float inv[32];
    const int tid = threadIdx.x;
    const int hw0 = blockIdx.x * 32;
    float* feat = g_feat + (size_t)slc * HW * Cc;

    if (tid < 32)
        inv[tid] = 1.0f / (g_att[(size_t)b * HW + hw0 + tid] + EPSV);

    const float4* src = reinterpret_cast<const float4*>(feat + (size_t)hw0 * Cc);
#pragma unroll
    for (int k = 0; k < 8; k++) {
        int i  = tid + k * 256;         // [0, 2048)
        int hw = i >> 6;                // 0..31 (pixel)
        int cq = i & 63;                // float4 index within 256 channels
        float4 v = src[i];
        int g  = cq >> 3;               // channel group (tile)
        int cc = (cq & 7) * 4;          // channel within tile
        float* d = &t[g * TSTRIDE + hw * 33 + cc];
        d[0] = v.x; d[1] = v.y; d[2] = v.z; d[3] = v.w;
    }
    __syncthreads();

    const int lane = tid & 31;
    const int g    = tid >> 5;          // warp -> channel group
    const int q    = lane >> 2;         // hw quad (4q..4q+3)
    const int jl   = lane & 3;          // channel sub-lane
    const float4 iv = *reinterpret_cast<const float4*>(&inv[4 * q]);
    const float* tg = &t[g * TSTRIDE];
#pragma unroll
    for (int it = 0; it < 8; it++) {
        const int cc = it * 4 + jl;     // channel within group
        float4 o;
        o.x = tg[(4 * q + 0) * 33 + cc] * iv.x;
        o.y = tg[(4 * q + 1) * 33 + cc] * iv.y;
        o.z = tg[(4 * q + 2) * 33 + cc] * iv.z;
        o.w = tg[(4 * q + 3) * 33 + cc] * iv.w;
        __stcs(reinterpret_cast<float4*>(
            out + ((size_t)b * Cc + g * 32 + cc) * HW + hw0 + 4 * q), o);
    }

    // Re-zero this block's scratch region (all loads above completed).
    float4* fz = reinterpret_cast<float4*>(feat + (size_t)hw0 * Cc);
    float4 z = make_float4(0.f, 0.f, 0.f, 0.f);
#pragma unroll
    for (int k = 0; k < 8; k++)
        fz[tid + k * 256] = z;
    if (tid < 32)
        g_att[(size_t)b * HW + hw0 + tid] = 0.f;
}

// ---------------------------------------------------------------- launch
// 16 independent (scatter,div) pairs, one batch each, round-robin over 4
// streams (origin + 3) with capture-safe event fork/join. Scratch slice
// reuse within a stream is ordered by stream order.
extern "C" void kernel_launch(void* const* d_in, const int* in_sizes, int n_in,
                              void* d_out, int out_size) {
    const float* x  = (const float*)d_in[0];   // [16,256,128,128]
    const float* cw = (const float*)d_in[1];   // [3,256]
    const float* cb = (const float*)d_in[2];   // [3]
    float* out  = (float*)d_out;                        // [B,C,HW]
    float* offo = out + (size_t)Bs * Cc * HW;           // [B,2,H,W]

    static cudaStream_t st[NSLC] = {nullptr, nullptr, nullptr, nullptr};
    static cudaEvent_t  efork = nullptr;
    static cudaEvent_t  ejoin[NSLC] = {nullptr, nullptr, nullptr, nullptr};
    if (efork == nullptr) {            // host-side resource init only
        st[0] = (cudaStream_t)0;       // capture-origin stream
        cudaEventCreateWithFlags(&efork, cudaEventDisableTiming);
        for (int i = 1; i < NSLC; i++) {
            cudaStreamCreateWithFlags(&st[i], cudaStreamNonBlocking);
            cudaEventCreateWithFlags(&ejoin[i], cudaEventDisableTiming);
        }
    }

    cudaEventRecord(efork, st[0]);
    for (int i = 1; i < NSLC; i++)
        cudaStreamWaitEvent(st[i], efork, 0);

    for (int b = 0; b < Bs; b++) {
        const int s = b & (NSLC - 1);
        k_scatter<<<HW / PIX, 256, 0, st[s]>>>(x, cw, cb, offo, b, s);
        k_div<<<HW / 32, 256, 0, st[s]>>>(out, b, s);
    }

    for (int i = 1; i < NSLC; i++) {
        cudaEventRecord(ejoin[i], st[i]);
        cudaStreamWaitEvent(st[0], ejoin[i], 0);
    }
}

// round 17
// speedup vs baseline: 1.2567x; 1.0764x over previous
#include <cuda_runtime.h>
#include <math.h>

#define Bs   16
#define Cc   256
#define Hh   128
#define Ww   128
#define HW   16384
#define NSLC 4           // ping-pong scratch slices / streams
#define PIX  32          // pixels per scatter block
#define SS   258         // smem row stride: lane*258 mod 32 = 2-way STS conflict (best found)
#define EPSV 1e-05f
#define TSTRIDE 1064     // words per transpose tile (32*33 + 8 pad)

// FOUR ping-pong scratch slices [NSLC][HW][C] (16 MB each, 64 MB total,
// L2-resident): batch b uses slice b%4 on stream b%4. g_att full size
// [Bs][HW] (batch-disjoint). Zero-initialized at load; k_div restores zeros
// after consumption (separate pass AFTER reads complete — R3 lesson: never
// store to a line with a pending same-thread load miss), so graph replays
// are deterministic. Streaming data (x, out, offo) uses evict-first hints
// (__ldcs/__stcs) so it cannot evict scratch from L2.
__device__ float g_feat[(size_t)NSLC * HW * Cc];
__device__ float g_att[(size_t)Bs * HW];

// -------------------------------------------- fused conv + scatter
// NUMERICS FROZEN (R8/R9 lesson): the strided-by-8 fp32 summation order
// (warp w owns channels {8k+w}, serial fmaf over k; warp0 reduce in w-order
// seeded with cb) correlates with the reference's own fp32 rounding at the
// round(dest) boundaries -> rel_err 8.8778e-4 stable. Do not reorder.
// R15 win: warp0 publishes s_att/s_idx BEFORE the barrier and defers its
// offo stores + g_att atomic until after it.
__global__ __launch_bounds__(256) void k_scatter(
    const float* __restrict__ x, const float* __restrict__ cw,
    const float* __restrict__ cb, float* __restrict__ offo, int b, int slc) {
    __shared__ float s_x[PIX * SS];     // 33 KB tile, [pixel][channel]
    __shared__ float s_w[3 * Cc];
    __shared__ float s_red[3 * 8 * 32];
    __shared__ float s_att[PIX];
    __shared__ int   s_idx[PIX];

    const int tid  = threadIdx.x;
    const int lane = tid & 31;
    const int warp = tid >> 5;
    const int hw0  = blockIdx.x * PIX;
    float* feat = g_feat + (size_t)slc * HW * Cc;

    for (int i = tid; i < 3 * Cc; i += 256) s_w[i] = cw[i];
    __syncthreads();

    const float* xb = x + (size_t)b * Cc * HW + hw0;
    float a0 = 0.f, a1 = 0.f, a2 = 0.f;
#pragma unroll
    for (int k = 0; k < Cc / 8; k++) {
        int c = k * 8 + warp;                         // warp owns channel slice
        float v = __ldcs(xb + (size_t)c * HW + lane); // streaming: read-once x
        s_x[lane * SS + c] = v;
        a0 = fmaf(v, s_w[c],          a0);
        a1 = fmaf(v, s_w[Cc + c],     a1);
        a2 = fmaf(v, s_w[2 * Cc + c], a2);
    }
    s_red[(0 * 8 + warp) * 32 + lane] = a0;
    s_red[(1 * 8 + warp) * 32 + lane] = a1;
    s_red[(2 * 8 + warp) * 32 + lane] = a2;
    __syncthreads();

    float offy = 0.f, offx = 0.f, att = 0.f;
    int idx = 0;
    if (warp == 0) {                    // lane == pixel within tile
        float r0 = cb[0], r1 = cb[1], r2 = cb[2];
#pragma unroll
        for (int w = 0; w < 8; w++) {
            r0 += s_red[w * 32 + lane];
            r1 += s_red[(8 + w) * 32 + lane];
            r2 += s_red[(16 + w) * 32 + lane];
        }
        offy = r0 * (float)Hh;
        offx = r1 * (float)Ww;
        att  = expf(r2);
        int hw = hw0 + lane;
        int hh = hw >> 7, wc = hw & 127;
        // round-half-even (rintf) then clip, matching jnp.round + clip
        int iy = (int)fminf(fmaxf(rintf((float)hh + offy), 0.f), 127.f);
        int ix = (int)fminf(fmaxf(rintf((float)wc + offx), 0.f), 127.f);
        idx = (iy << 7) + ix;
        s_att[lane] = att;              // publish for the other warps…
        s_idx[lane] = idx;
    }
    __syncthreads();

    if (warp == 0) {                    // …then do global writes off-path
        size_t ob = (size_t)b * 2 * HW + hw0 + lane;  // offset: [B][2][H][W]
        __stcs(offo + ob,      offy);                 // streaming: write-once
        __stcs(offo + ob + HW, offx);
        atomicAdd(&g_att[(size_t)b * HW + idx], att);
    }

    // Scatter: each warp handles 4 pixels; per pixel, 2 x red.v4 per lane
    // covering a contiguous 1KB destination row feat[idx][:].
#pragma unroll
    for (int p = warp; p < PIX; p += 8) {
        float attp = s_att[p];
        float* dst = feat + (size_t)s_idx[p] * Cc;
        const float* src = s_x + p * SS;
#pragma unroll
        for (int r = 0; r < 2; r++) {
            int c0 = r * 128 + 4 * lane;
            float2 u = *reinterpret_cast<const float2*>(src + c0);
            float2 v = *reinterpret_cast<const float2*>(src + c0 + 2);
            asm volatile(
                "red.global.add.v4.f32 [%0], {%1, %2, %3, %4};" ::
                "l"(dst + c0),
                "f"(u.x * attp), "f"(u.y * attp),
                "f"(v.x * attp), "f"(v.y * attp)
                : "memory");
        }
    }
}

// ----------------- normalize + transpose to [B][C][HW] + re-zero scratch
// R16 change — UNTOUCHED-ROW SKIP: g_att[d]==0.0 exactly <=> no source
// scattered to d <=> scratch row d is still all-zero. For those rows we skip
// the 8 LDG.128 (substituting zero STS into the tile — avoids stale-smem NaN)
// AND the 8 zero-STG.128 (row already zero). Mask via warp0 ballot; per
// (warp,k) the hw row is warp-uniform -> divergence-free whole-line skips.
// out for untouched pixels = 0 * inv = 0, matching reference 0/EPS = 0.
// Load phase: 8 independent coalesced LDG.128 per thread (MLP=8) into 8
// padded 32x33 smem tiles. Store phase: warp g owns channel group g; lane
// (q,jl) gathers 4 hw per channel (conflict-free) and writes streaming
// STG.128. Zero pass after consumption (R3 lesson preserved).
__global__ __launch_bounds__(256) void k_div(float* __restrict__ out, int b,
                                             int slc) {
    __shared__ float t[8 * TSTRIDE];    // ~34 KB
    __shared__ __align__(16) float inv[32];
    __shared__ unsigned s_mask;
    const int tid = threadIdx.x;
    const int hw0 = blockIdx.x * 32;
    float* feat = g_feat + (size_t)slc * HW * Cc;

    if (tid < 32) {
        float a = g_att[(size_t)b * HW + hw0 + tid];
        unsigned m = __ballot_sync(0xffffffffu, a != 0.0f);
        inv[tid] = 1.0f / (a + EPSV);
        if (tid == 0) s_mask = m;
    }
    __syncthreads();
    const unsigned mask = s_mask;

    const float4* src = reinterpret_cast<const float4*>(feat + (size_t)hw0 * Cc);
    const float4 z4 = make_float4(0.f, 0.f, 0.f, 0.f);
#pragma unroll
    for (int k = 0; k < 8; k++) {
        int i  = tid + k * 256;         // [0, 2048)
        int hw = i >> 6;                // 0..31 (pixel); warp-uniform per k
        float4 v = z4;
        if ((mask >> hw) & 1u)          // touched row -> real load
            v = src[i];
        int cq = i & 63;                // float4 index within 256 channels
        int g  = cq >> 3;               // channel group (tile)
        int cc = (cq & 7) * 4;          // channel within tile
        float* d = &t[g * TSTRIDE + hw * 33 + cc];
        d[0] = v.x; d[1] = v.y; d[2] = v.z; d[3] = v.w;
    }
    __syncthreads();

    const int lane = tid & 31;
    const int g    = tid >> 5;          // warp -> channel group
    const int q    = lane >> 2;         // hw quad (4q..4q+3)
    const int jl   = lane & 3;          // channel sub-lane
    const float4 iv = *reinterpret_cast<const float4*>(&inv[4 * q]);
    const float* tg = &t[g * TSTRIDE];
#pragma unroll
    for (int it = 0; it < 8; it++) {
        const int cc = it * 4 + jl;     // channel within group
        float4 o;
        o.x = tg[(4 * q + 0) * 33 + cc] * iv.x;
        o.y = tg[(4 * q + 1) * 33 + cc] * iv.y;
        o.z = tg[(4 * q + 2) * 33 + cc] * iv.z;
        o.w = tg[(4 * q + 3) * 33 + cc] * iv.w;
        __stcs(reinterpret_cast<float4*>(
            out + ((size_t)b * Cc + g * 32 + cc) * HW + hw0 + 4 * q), o);
    }

    // Re-zero only TOUCHED scratch rows (untouched are already zero); all
    // loads above completed, so no pending-miss hazard.
    float4* fz = reinterpret_cast<float4*>(feat + (size_t)hw0 * Cc);
#pragma unroll
    for (int k = 0; k < 8; k++) {
        int i  = tid + k * 256;
        int hw = i >> 6;                // warp-uniform per k
        if ((mask >> hw) & 1u)
            fz[i] = z4;
    }
    if (tid < 32 && ((mask >> tid) & 1u))
        g_att[(size_t)b * HW + hw0 + tid] = 0.f;
}

// ---------------------------------------------------------------- launch
// 16 independent (scatter,div) pairs, one batch each, round-robin over 4
// streams (origin + 3) with capture-safe event fork/join. Scratch slice
// reuse within a stream is ordered by stream order.
extern "C" void kernel_launch(void* const* d_in, const int* in_sizes, int n_in,
                              void* d_out, int out_size) {
    const float* x  = (const float*)d_in[0];   // [16,256,128,128]
    const float* cw = (const float*)d_in[1];   // [3,256]
    const float* cb = (const float*)d_in[2];   // [3]
    float* out  = (float*)d_out;                        // [B,C,HW]
    float* offo = out + (size_t)Bs * Cc * HW;           // [B,2,H,W]

    static cudaStream_t st[NSLC] = {nullptr, nullptr, nullptr, nullptr};
    static cudaEvent_t  efork = nullptr;
    static cudaEvent_t  ejoin[NSLC] = {nullptr, nullptr, nullptr, nullptr};
    if (efork == nullptr) {            // host-side resource init only
        st[0] = (cudaStream_t)0;       // capture-origin stream
        cudaEventCreateWithFlags(&efork, cudaEventDisableTiming);
        for (int i = 1; i < NSLC; i++) {
            cudaStreamCreateWithFlags(&st[i], cudaStreamNonBlocking);
            cudaEventCreateWithFlags(&ejoin[i], cudaEventDisableTiming);
        }
    }

    cudaEventRecord(efork, st[0]);
    for (int i = 1; i < NSLC; i++)
        cudaStreamWaitEvent(st[i], efork, 0);

    for (int b = 0; b < Bs; b++) {
        const int s = b & (NSLC - 1);
        k_scatter<<<HW / PIX, 256, 0, st[s]>>>(x, cw, cb, offo, b, s);
        k_div<<<HW / 32, 256, 0, st[s]>>>(out, b, s);
    }

    for (int i = 1; i < NSLC; i++) {
        cudaEventRecord(ejoin[i], st[i]);
        cudaStreamWaitEvent(st[0], ejoin[i], 0);
    }
}